// round 9
// baseline (speedup 1.0000x reference)
#include <cuda_runtime.h>
#include <cuda_bf16.h>

#define NN 100000
#define NE 3200000
#define TPB 256
#define BPSM 6

// ---------------- scratch (device globals: allocation-free) ----------------
__device__ int2     g_edges[NE];   // packed edges (int64 input path only)
__device__ int      g_deg[NN];
__device__ float4   g_t4[NN];      // scaled node features (gather source)
__device__ float4   g_aggA[NN];    // layer-1 accumulator
__device__ float4   g_aggB[NN];    // layer-2 accumulator
__device__ float2   g_t2[NN];      // layer-3 scaled features
__device__ float2   g_agg2[NN];    // layer-3 accumulator
__device__ int      g_idx32;
__device__ unsigned g_bcnt;        // barrier ticket counter (zero-init)
__device__ unsigned g_bgen;        // barrier generation (monotonic across launches)

// ---------------- grid-wide barrier (all blocks resident by construction) ------
__device__ __forceinline__ void gbar(int nb, unsigned& mygen) {
    __syncthreads();
    if (threadIdx.x == 0) {
        __threadfence();
        if (atomicAdd(&g_bcnt, 1u) == (unsigned)(nb - 1)) {
            atomicExch(&g_bcnt, 0u);
            __threadfence();
            atomicExch(&g_bgen, mygen + 1u);
        } else {
            while (atomicAdd(&g_bgen, 0u) < mygen + 1u) __nanosleep(32);
        }
    }
    __syncthreads();
    mygen += 1u;
}

// ---------------- the whole GCN in one persistent kernel ----------------
__global__ void __launch_bounds__(TPB, BPSM) k_gcn(
    const void* __restrict__ eiv,
    const float* __restrict__ x,
    const float* __restrict__ W1, const float* __restrict__ b1,
    const float* __restrict__ W2, const float* __restrict__ b2,
    const float* __restrict__ W3, const float* __restrict__ b3,
    const float* __restrict__ Wc, const float* __restrict__ bc,
    float* __restrict__ out, int write_h, int nb)
{
    __shared__ float sW[512];
    const int tid  = threadIdx.x;
    const int gtid = blockIdx.x * TPB + tid;
    const int T    = nb * TPB;
    unsigned mygen = g_bgen;                 // stable at launch; works across replays

    for (int i = tid; i < 512; i += TPB) sW[i] = W1[i];   // W1 [128,4]

    // ---- phase 0: deg=1 init + dtype detect ----
    for (int v = gtid; v < NN; v += T) g_deg[v] = 1;
    if (blockIdx.x == 0 && tid < 32) {
        long long val = ((const long long*)eiv)[tid];
        unsigned bad = __ballot_sync(0xffffffffu, val < 0 || val >= NN);
        if (tid == 0) g_idx32 = bad ? 1 : 0;
    }
    gbar(nb, mygen);

    // ---- phase 1: degree histogram (+ pack for int64 input) ----
    const bool i32 = (g_idx32 != 0);
    const int* ei32 = (const int*)eiv;
    if (i32) {
        for (int b = gtid * 4; b < NE; b += T * 4) {
            int4 cc = __ldg((const int4*)(ei32 + NE + b));
            atomicAdd(&g_deg[cc.x], 1);
            atomicAdd(&g_deg[cc.y], 1);
            atomicAdd(&g_deg[cc.z], 1);
            atomicAdd(&g_deg[cc.w], 1);
        }
    } else {
        const long long* ei = (const long long*)eiv;
        for (int e = gtid; e < NE; e += T) {
            int r = (int)ei[e];
            int c = (int)ei[NE + e];
            g_edges[e] = make_int2(r, c);
            atomicAdd(&g_deg[c], 1);
        }
    }
    gbar(nb, mygen);

    // ---- phase 2: layer-1 transform, warp per node: t4 = (x@W1)*dinv; aggA = t4 ----
    {
        const int gw = gtid >> 5, lane = tid & 31, W = T >> 5;
        for (int v = gw; v < NN; v += W) {
            float4 xr = __ldg((const float4*)x + (size_t)v * 32 + lane);
            float xs[4] = {xr.x, xr.y, xr.z, xr.w};
            float acc[4] = {0.f, 0.f, 0.f, 0.f};
            #pragma unroll
            for (int i = 0; i < 4; i++) {
                int k = lane * 4 + i;
                #pragma unroll
                for (int j = 0; j < 4; j++) acc[j] += xs[i] * sW[k * 4 + j];
            }
            #pragma unroll
            for (int o = 16; o > 0; o >>= 1) {
                #pragma unroll
                for (int j = 0; j < 4; j++)
                    acc[j] += __shfl_xor_sync(0xffffffffu, acc[j], o);
            }
            if (lane == 0) {
                float d = rsqrtf((float)g_deg[v]);
                float4 t = make_float4(acc[0]*d, acc[1]*d, acc[2]*d, acc[3]*d);
                g_t4[v]   = t;
                g_aggA[v] = t;
            }
        }
    }
    gbar(nb, mygen);

    // ---- phase 3: scatter 1: aggA[r] += t4[c] ----
    if (i32) {
        for (int b = gtid * 4; b < NE; b += T * 4) {
            int4 rr = __ldg((const int4*)(ei32 + b));
            int4 cc = __ldg((const int4*)(ei32 + NE + b));
            float4 v0 = __ldg(g_t4 + cc.x), v1 = __ldg(g_t4 + cc.y);
            float4 v2 = __ldg(g_t4 + cc.z), v3 = __ldg(g_t4 + cc.w);
            asm volatile("red.global.add.v4.f32 [%0], {%1,%2,%3,%4};" :: "l"(g_aggA + rr.x), "f"(v0.x),"f"(v0.y),"f"(v0.z),"f"(v0.w) : "memory");
            asm volatile("red.global.add.v4.f32 [%0], {%1,%2,%3,%4};" :: "l"(g_aggA + rr.y), "f"(v1.x),"f"(v1.y),"f"(v1.z),"f"(v1.w) : "memory");
            asm volatile("red.global.add.v4.f32 [%0], {%1,%2,%3,%4};" :: "l"(g_aggA + rr.z), "f"(v2.x),"f"(v2.y),"f"(v2.z),"f"(v2.w) : "memory");
            asm volatile("red.global.add.v4.f32 [%0], {%1,%2,%3,%4};" :: "l"(g_aggA + rr.w), "f"(v3.x),"f"(v3.y),"f"(v3.z),"f"(v3.w) : "memory");
        }
    } else {
        for (int b = gtid * 2; b < NE; b += T * 2) {
            int4 p = *(const int4*)(g_edges + b);
            float4 v0 = __ldg(g_t4 + p.y), v1 = __ldg(g_t4 + p.w);
            asm volatile("red.global.add.v4.f32 [%0], {%1,%2,%3,%4};" :: "l"(g_aggA + p.x), "f"(v0.x),"f"(v0.y),"f"(v0.z),"f"(v0.w) : "memory");
            asm volatile("red.global.add.v4.f32 [%0], {%1,%2,%3,%4};" :: "l"(g_aggA + p.z), "f"(v1.x),"f"(v1.y),"f"(v1.z),"f"(v1.w) : "memory");
        }
    }
    gbar(nb, mygen);

    // ---- phase 4: layer-2 transform ----
    for (int v = gtid; v < NN; v += T) {
        float d  = rsqrtf((float)g_deg[v]);
        float4 a = g_aggA[v];
        float h0 = tanhf(fmaf(a.x, d, __ldg(b1 + 0)));
        float h1 = tanhf(fmaf(a.y, d, __ldg(b1 + 1)));
        float h2 = tanhf(fmaf(a.z, d, __ldg(b1 + 2)));
        float h3 = tanhf(fmaf(a.w, d, __ldg(b1 + 3)));
        float t[4];
        #pragma unroll
        for (int j = 0; j < 4; j++)
            t[j] = (h0 * __ldg(W2 + j)     + h1 * __ldg(W2 + 4 + j)
                  + h2 * __ldg(W2 + 8 + j) + h3 * __ldg(W2 + 12 + j)) * d;
        float4 tv = make_float4(t[0], t[1], t[2], t[3]);
        g_t4[v]   = tv;
        g_aggB[v] = tv;
    }
    gbar(nb, mygen);

    // ---- phase 5: scatter 2: aggB[r] += t4[c] ----
    if (i32) {
        for (int b = gtid * 4; b < NE; b += T * 4) {
            int4 rr = __ldg((const int4*)(ei32 + b));
            int4 cc = __ldg((const int4*)(ei32 + NE + b));
            float4 v0 = __ldg(g_t4 + cc.x), v1 = __ldg(g_t4 + cc.y);
            float4 v2 = __ldg(g_t4 + cc.z), v3 = __ldg(g_t4 + cc.w);
            asm volatile("red.global.add.v4.f32 [%0], {%1,%2,%3,%4};" :: "l"(g_aggB + rr.x), "f"(v0.x),"f"(v0.y),"f"(v0.z),"f"(v0.w) : "memory");
            asm volatile("red.global.add.v4.f32 [%0], {%1,%2,%3,%4};" :: "l"(g_aggB + rr.y), "f"(v1.x),"f"(v1.y),"f"(v1.z),"f"(v1.w) : "memory");
            asm volatile("red.global.add.v4.f32 [%0], {%1,%2,%3,%4};" :: "l"(g_aggB + rr.z), "f"(v2.x),"f"(v2.y),"f"(v2.z),"f"(v2.w) : "memory");
            asm volatile("red.global.add.v4.f32 [%0], {%1,%2,%3,%4};" :: "l"(g_aggB + rr.w), "f"(v3.x),"f"(v3.y),"f"(v3.z),"f"(v3.w) : "memory");
        }
    } else {
        for (int b = gtid * 2; b < NE; b += T * 2) {
            int4 p = *(const int4*)(g_edges + b);
            float4 v0 = __ldg(g_t4 + p.y), v1 = __ldg(g_t4 + p.w);
            asm volatile("red.global.add.v4.f32 [%0], {%1,%2,%3,%4};" :: "l"(g_aggB + p.x), "f"(v0.x),"f"(v0.y),"f"(v0.z),"f"(v0.w) : "memory");
            asm volatile("red.global.add.v4.f32 [%0], {%1,%2,%3,%4};" :: "l"(g_aggB + p.z), "f"(v1.x),"f"(v1.y),"f"(v1.z),"f"(v1.w) : "memory");
        }
    }
    gbar(nb, mygen);

    // ---- phase 6: layer-3 transform ----
    for (int v = gtid; v < NN; v += T) {
        float d  = rsqrtf((float)g_deg[v]);
        float4 a = g_aggB[v];
        float h0 = tanhf(fmaf(a.x, d, __ldg(b2 + 0)));
        float h1 = tanhf(fmaf(a.y, d, __ldg(b2 + 1)));
        float h2 = tanhf(fmaf(a.z, d, __ldg(b2 + 2)));
        float h3 = tanhf(fmaf(a.w, d, __ldg(b2 + 3)));
        float t0 = (h0 * __ldg(W3 + 0) + h1 * __ldg(W3 + 2)
                  + h2 * __ldg(W3 + 4) + h3 * __ldg(W3 + 6)) * d;
        float t1 = (h0 * __ldg(W3 + 1) + h1 * __ldg(W3 + 3)
                  + h2 * __ldg(W3 + 5) + h3 * __ldg(W3 + 7)) * d;
        float2 tv = make_float2(t0, t1);
        g_t2[v]   = tv;
        g_agg2[v] = tv;
    }
    gbar(nb, mygen);

    // ---- phase 7: scatter 3 (v2): agg2[r] += t2[c] ----
    if (i32) {
        for (int b = gtid * 4; b < NE; b += T * 4) {
            int4 rr = __ldg((const int4*)(ei32 + b));
            int4 cc = __ldg((const int4*)(ei32 + NE + b));
            float2 v0 = __ldg(g_t2 + cc.x), v1 = __ldg(g_t2 + cc.y);
            float2 v2 = __ldg(g_t2 + cc.z), v3 = __ldg(g_t2 + cc.w);
            asm volatile("red.global.add.v2.f32 [%0], {%1,%2};" :: "l"(g_agg2 + rr.x), "f"(v0.x),"f"(v0.y) : "memory");
            asm volatile("red.global.add.v2.f32 [%0], {%1,%2};" :: "l"(g_agg2 + rr.y), "f"(v1.x),"f"(v1.y) : "memory");
            asm volatile("red.global.add.v2.f32 [%0], {%1,%2};" :: "l"(g_agg2 + rr.z), "f"(v2.x),"f"(v2.y) : "memory");
            asm volatile("red.global.add.v2.f32 [%0], {%1,%2};" :: "l"(g_agg2 + rr.w), "f"(v3.x),"f"(v3.y) : "memory");
        }
    } else {
        for (int b = gtid * 2; b < NE; b += T * 2) {
            int4 p = *(const int4*)(g_edges + b);
            float2 v0 = __ldg(g_t2 + p.y), v1 = __ldg(g_t2 + p.w);
            asm volatile("red.global.add.v2.f32 [%0], {%1,%2};" :: "l"(g_agg2 + p.x), "f"(v0.x),"f"(v0.y) : "memory");
            asm volatile("red.global.add.v2.f32 [%0], {%1,%2};" :: "l"(g_agg2 + p.z), "f"(v1.x),"f"(v1.y) : "memory");
        }
    }
    gbar(nb, mygen);

    // ---- phase 8: epilogue ----
    for (int v = gtid; v < NN; v += T) {
        float d  = rsqrtf((float)g_deg[v]);
        float2 a = g_agg2[v];
        float h0 = tanhf(fmaf(a.x, d, __ldg(b3 + 0)));
        float h1 = tanhf(fmaf(a.y, d, __ldg(b3 + 1)));
        float4 o;
        o.x = h0 * __ldg(Wc + 0) + h1 * __ldg(Wc + 4) + __ldg(bc + 0);
        o.y = h0 * __ldg(Wc + 1) + h1 * __ldg(Wc + 5) + __ldg(bc + 1);
        o.z = h0 * __ldg(Wc + 2) + h1 * __ldg(Wc + 6) + __ldg(bc + 2);
        o.w = h0 * __ldg(Wc + 3) + h1 * __ldg(Wc + 7) + __ldg(bc + 3);
        ((float4*)out)[v] = o;
        if (write_h)
            ((float2*)(out + 4 * NN))[v] = make_float2(h0, h1);
    }
}

// ---------------- host ----------------
extern "C" void kernel_launch(void* const* d_in, const int* in_sizes, int n_in,
                              void* d_out, int out_size) {
    const float* x  = (const float*)d_in[0];
    const void*  ei = d_in[1];
    const float* W1 = (const float*)d_in[2];
    const float* b1 = (const float*)d_in[3];
    const float* W2 = (const float*)d_in[4];
    const float* b2 = (const float*)d_in[5];
    const float* W3 = (const float*)d_in[6];
    const float* b3 = (const float*)d_in[7];
    const float* Wc = (const float*)d_in[8];
    const float* bc = (const float*)d_in[9];
    float* out = (float*)d_out;

    int nsm = 0;
    if (cudaDeviceGetAttribute(&nsm, cudaDevAttrMultiProcessorCount, 0) != cudaSuccess || nsm <= 0)
        nsm = 148;
    const int nb = nsm * BPSM;                    // fully resident by __launch_bounds__
    const int write_h = (out_size >= 6 * NN) ? 1 : 0;

    k_gcn<<<nb, TPB>>>(ei, x, W1, b1, W2, b2, W3, b3, Wc, bc, out, write_h, nb);
}

// round 11
// speedup vs baseline: 1.2754x; 1.2754x over previous
#include <cuda_runtime.h>
#include <cuda_bf16.h>

#define NN 100000
#define NE 3200000

// ---------------- scratch (device globals: allocation-free) ----------------
__device__ int2   g_edges[NE];   // packed edges (int64 input path only)
__device__ int    g_deg[NN];
__device__ float4 g_t4[NN];      // scaled node features (gather source)
__device__ float4 g_aggA[NN];    // layer-1 accumulator
__device__ float4 g_aggB[NN];    // layer-2 accumulator
__device__ float2 g_t2[NN];      // layer-3 scaled features
__device__ float2 g_agg2[NN];    // layer-3 accumulator
__device__ int    g_idx32;       // 1 if edge_index is int32

// ---------------- detect dtype (1 warp) + init degrees ----------------
__global__ void k_init(const long long* __restrict__ ei) {
    int v = blockIdx.x * blockDim.x + threadIdx.x;
    if (v < NN) g_deg[v] = 1;                       // self-loop
    if (blockIdx.x == 0 && threadIdx.x < 32) {
        long long val = ei[threadIdx.x];
        unsigned bad = __ballot_sync(0xffffffffu, val < 0 || val >= NN);
        if (threadIdx.x == 0) g_idx32 = bad ? 1 : 0;
    }
}

// ---------------- fused: GEMV (x@W1, unscaled) || degree histogram ----------------
// Blocks [0, GB): warp-per-node GEMV into g_t4 (raw). Blocks [GB, GB+HB): histogram.
// Independent resources (DRAM stream vs L2 atomics); no intra-kernel ordering needed.
#define GB 444
#define HB 444
__global__ void __launch_bounds__(256) k_fused(const void* __restrict__ eiv,
                                               const float* __restrict__ x,
                                               const float* __restrict__ W1) {
    if (blockIdx.x < GB) {
        __shared__ float sW[512];
        for (int i = threadIdx.x; i < 512; i += 256) sW[i] = W1[i];
        __syncthreads();
        const int lane = threadIdx.x & 31;
        const int warps = GB * 8;
        for (int v = (blockIdx.x * 256 + threadIdx.x) >> 5; v < NN; v += warps) {
            float4 xr = __ldg((const float4*)x + (size_t)v * 32 + lane);
            float xs[4] = {xr.x, xr.y, xr.z, xr.w};
            float acc[4] = {0.f, 0.f, 0.f, 0.f};
            #pragma unroll
            for (int i = 0; i < 4; i++) {
                int k = lane * 4 + i;
                #pragma unroll
                for (int j = 0; j < 4; j++) acc[j] += xs[i] * sW[k * 4 + j];
            }
            #pragma unroll
            for (int o = 16; o > 0; o >>= 1) {
                #pragma unroll
                for (int j = 0; j < 4; j++)
                    acc[j] += __shfl_xor_sync(0xffffffffu, acc[j], o);
            }
            if (lane == 0)
                g_t4[v] = make_float4(acc[0], acc[1], acc[2], acc[3]);  // unscaled
        }
    } else {
        const int gt = (blockIdx.x - GB) * 256 + threadIdx.x;
        const int T  = HB * 256;
        if (g_idx32) {
            const int* ei32 = (const int*)eiv;
            for (int b = gt * 4; b < NE; b += T * 4) {
                int4 cc = __ldg((const int4*)(ei32 + NE + b));
                atomicAdd(&g_deg[cc.x], 1);
                atomicAdd(&g_deg[cc.y], 1);
                atomicAdd(&g_deg[cc.z], 1);
                atomicAdd(&g_deg[cc.w], 1);
            }
        } else {
            const long long* ei = (const long long*)eiv;
            for (int e = gt; e < NE; e += T) {
                int r = (int)ei[e];
                int c = (int)ei[NE + e];
                g_edges[e] = make_int2(r, c);
                atomicAdd(&g_deg[c], 1);
            }
        }
    }
}

// ---------------- scale: t4 *= dinv ; aggA = t4 (self-loop) ----------------
__global__ void __launch_bounds__(256) k_scale() {
    int v = blockIdx.x * blockDim.x + threadIdx.x;
    if (v >= NN) return;
    float d  = rsqrtf((float)g_deg[v]);
    float4 a = g_t4[v];
    float4 t = make_float4(a.x * d, a.y * d, a.z * d, a.w * d);
    g_t4[v]   = t;
    g_aggA[v] = t;
}

// ---------------- edge scatter: agg[row] += t4[col]  (2 edges/thread) ----------
template <int PHASE>   // 0: aggA, 1: aggB
__global__ void __launch_bounds__(256) k_scatter4(const int* __restrict__ ei32) {
    int base = (blockIdx.x * 256 + threadIdx.x) * 2;
    if (base >= NE) return;
    float4* agg = (PHASE == 0) ? g_aggA : g_aggB;
    int r0, c0, r1, c1;
    if (g_idx32) {
        int2 rr = __ldg((const int2*)(ei32 + base));
        int2 cc = __ldg((const int2*)(ei32 + NE + base));
        r0 = rr.x; r1 = rr.y; c0 = cc.x; c1 = cc.y;
    } else {
        int4 p = *(const int4*)(g_edges + base);
        r0 = p.x; c0 = p.y; r1 = p.z; c1 = p.w;
    }
    float4 v0 = __ldg(g_t4 + c0);
    float4 v1 = __ldg(g_t4 + c1);
    asm volatile("red.global.add.v4.f32 [%0], {%1,%2,%3,%4};"
                 :: "l"(agg + r0), "f"(v0.x), "f"(v0.y), "f"(v0.z), "f"(v0.w) : "memory");
    asm volatile("red.global.add.v4.f32 [%0], {%1,%2,%3,%4};"
                 :: "l"(agg + r1), "f"(v1.x), "f"(v1.y), "f"(v1.z), "f"(v1.w) : "memory");
}

__global__ void __launch_bounds__(256) k_scatter2(const int* __restrict__ ei32) {
    int base = (blockIdx.x * 256 + threadIdx.x) * 2;
    if (base >= NE) return;
    int r0, c0, r1, c1;
    if (g_idx32) {
        int2 rr = __ldg((const int2*)(ei32 + base));
        int2 cc = __ldg((const int2*)(ei32 + NE + base));
        r0 = rr.x; r1 = rr.y; c0 = cc.x; c1 = cc.y;
    } else {
        int4 p = *(const int4*)(g_edges + base);
        r0 = p.x; c0 = p.y; r1 = p.z; c1 = p.w;
    }
    float2 v0 = __ldg(g_t2 + c0);
    float2 v1 = __ldg(g_t2 + c1);
    asm volatile("red.global.add.v2.f32 [%0], {%1,%2};"
                 :: "l"(g_agg2 + r0), "f"(v0.x), "f"(v0.y) : "memory");
    asm volatile("red.global.add.v2.f32 [%0], {%1,%2};"
                 :: "l"(g_agg2 + r1), "f"(v1.x), "f"(v1.y) : "memory");
}

// ---------------- layer 2 transform ----------------
__global__ void __launch_bounds__(256) k_l2(const float* __restrict__ W2,
                                            const float* __restrict__ b1) {
    int v = blockIdx.x * blockDim.x + threadIdx.x;
    if (v >= NN) return;
    float d  = rsqrtf((float)g_deg[v]);
    float4 a = g_aggA[v];
    float h0 = tanhf(fmaf(a.x, d, __ldg(b1 + 0)));
    float h1 = tanhf(fmaf(a.y, d, __ldg(b1 + 1)));
    float h2 = tanhf(fmaf(a.z, d, __ldg(b1 + 2)));
    float h3 = tanhf(fmaf(a.w, d, __ldg(b1 + 3)));
    float t[4];
    #pragma unroll
    for (int j = 0; j < 4; j++)
        t[j] = (h0 * __ldg(W2 + j)     + h1 * __ldg(W2 + 4 + j)
              + h2 * __ldg(W2 + 8 + j) + h3 * __ldg(W2 + 12 + j)) * d;
    float4 tv = make_float4(t[0], t[1], t[2], t[3]);
    g_t4[v]   = tv;
    g_aggB[v] = tv;
}

// ---------------- layer 3 transform ----------------
__global__ void __launch_bounds__(256) k_l3(const float* __restrict__ W3,
                                            const float* __restrict__ b2) {
    int v = blockIdx.x * blockDim.x + threadIdx.x;
    if (v >= NN) return;
    float d  = rsqrtf((float)g_deg[v]);
    float4 a = g_aggB[v];
    float h0 = tanhf(fmaf(a.x, d, __ldg(b2 + 0)));
    float h1 = tanhf(fmaf(a.y, d, __ldg(b2 + 1)));
    float h2 = tanhf(fmaf(a.z, d, __ldg(b2 + 2)));
    float h3 = tanhf(fmaf(a.w, d, __ldg(b2 + 3)));
    float t0 = (h0 * __ldg(W3 + 0) + h1 * __ldg(W3 + 2)
              + h2 * __ldg(W3 + 4) + h3 * __ldg(W3 + 6)) * d;
    float t1 = (h0 * __ldg(W3 + 1) + h1 * __ldg(W3 + 3)
              + h2 * __ldg(W3 + 5) + h3 * __ldg(W3 + 7)) * d;
    float2 tv = make_float2(t0, t1);
    g_t2[v]   = tv;
    g_agg2[v] = tv;
}

// ---------------- epilogue ----------------
__global__ void __launch_bounds__(256) k_final(const float* __restrict__ b3,
                                               const float* __restrict__ Wc,
                                               const float* __restrict__ bc,
                                               float* __restrict__ out,
                                               int write_h) {
    int v = blockIdx.x * blockDim.x + threadIdx.x;
    if (v >= NN) return;
    float d  = rsqrtf((float)g_deg[v]);
    float2 a = g_agg2[v];
    float h0 = tanhf(fmaf(a.x, d, __ldg(b3 + 0)));
    float h1 = tanhf(fmaf(a.y, d, __ldg(b3 + 1)));
    float4 o;
    o.x = h0 * __ldg(Wc + 0) + h1 * __ldg(Wc + 4) + __ldg(bc + 0);
    o.y = h0 * __ldg(Wc + 1) + h1 * __ldg(Wc + 5) + __ldg(bc + 1);
    o.z = h0 * __ldg(Wc + 2) + h1 * __ldg(Wc + 6) + __ldg(bc + 2);
    o.w = h0 * __ldg(Wc + 3) + h1 * __ldg(Wc + 7) + __ldg(bc + 3);
    ((float4*)out)[v] = o;                                  // out [N,4]
    if (write_h)
        ((float2*)(out + 4 * NN))[v] = make_float2(h0, h1); // h [N,2]
}

// ---------------- host ----------------
extern "C" void kernel_launch(void* const* d_in, const int* in_sizes, int n_in,
                              void* d_out, int out_size) {
    const float* x  = (const float*)d_in[0];
    const void*  ei = d_in[1];
    const float* W1 = (const float*)d_in[2];
    const float* b1 = (const float*)d_in[3];
    const float* W2 = (const float*)d_in[4];
    const float* b2 = (const float*)d_in[5];
    const float* W3 = (const float*)d_in[6];
    const float* b3 = (const float*)d_in[7];
    const float* Wc = (const float*)d_in[8];
    const float* bc = (const float*)d_in[9];
    float* out = (float*)d_out;

    const int nbN  = (NN + 255) / 256;
    const int nbE2 = NE / (256 * 2);            // 2 edges/thread (exact: 6250)
    const int write_h = (out_size >= 6 * NN) ? 1 : 0;

    k_init <<<nbN, 256>>>((const long long*)ei);
    k_fused<<<GB + HB, 256>>>(ei, x, W1);       // GEMV || histogram
    k_scale<<<nbN, 256>>>();

    k_scatter4<0><<<nbE2, 256>>>((const int*)ei);
    k_l2         <<<nbN, 256>>>(W2, b1);
    k_scatter4<1><<<nbE2, 256>>>((const int*)ei);
    k_l3         <<<nbN, 256>>>(W3, b2);
    k_scatter2   <<<nbE2, 256>>>((const int*)ei);
    k_final      <<<nbN, 256>>>(b3, Wc, bc, out, write_h);
}

// round 12
// speedup vs baseline: 1.3134x; 1.0298x over previous
#include <cuda_runtime.h>
#include <cuda_bf16.h>

#define NN 100000
#define NE 3200000

// ---------------- scratch (device globals: allocation-free) ----------------
__device__ int2   g_edges[NE];   // packed edges (int64 input path only)
__device__ int    g_deg[NN];     // zeroed by memsetAsync; true degree = g_deg+1
__device__ float4 g_t4[NN];      // scaled node features (gather source)
__device__ float4 g_aggA[NN];    // layer-1 accumulator
__device__ float4 g_aggB[NN];    // layer-2 accumulator
__device__ float2 g_t2[NN];      // layer-3 scaled features
__device__ float2 g_agg2[NN];    // layer-3 accumulator
__device__ int    g_idx32;       // 1 if edge_index is int32 (written by k_fused)

// ---------------- fused: GEMV (x@W1, unscaled) || degree histogram ----------------
// Blocks [0, GB): warp-per-node GEMV into g_t4 (raw).
// Blocks [GB, GB+HB): dtype self-detect + degree histogram (+ pack for int64).
#define GB 444
#define HB 444
__global__ void __launch_bounds__(256) k_fused(const void* __restrict__ eiv,
                                               const float* __restrict__ x,
                                               const float* __restrict__ W1) {
    if (blockIdx.x < GB) {
        __shared__ float sW[512];
        for (int i = threadIdx.x; i < 512; i += 256) sW[i] = W1[i];
        __syncthreads();
        const int lane = threadIdx.x & 31;
        const int warps = GB * 8;
        for (int v = (blockIdx.x * 256 + threadIdx.x) >> 5; v < NN; v += warps) {
            float4 xr = __ldg((const float4*)x + (size_t)v * 32 + lane);
            float xs[4] = {xr.x, xr.y, xr.z, xr.w};
            float acc[4] = {0.f, 0.f, 0.f, 0.f};
            #pragma unroll
            for (int i = 0; i < 4; i++) {
                int k = lane * 4 + i;
                #pragma unroll
                for (int j = 0; j < 4; j++) acc[j] += xs[i] * sW[k * 4 + j];
            }
            #pragma unroll
            for (int o = 16; o > 0; o >>= 1) {
                #pragma unroll
                for (int j = 0; j < 4; j++)
                    acc[j] += __shfl_xor_sync(0xffffffffu, acc[j], o);
            }
            if (lane == 0)
                g_t4[v] = make_float4(acc[0], acc[1], acc[2], acc[3]);  // unscaled
        }
    } else {
        // per-block dtype self-detection (no separate kernel / ordering dep)
        __shared__ int s_i32;
        if (threadIdx.x < 32) {
            long long val = ((const long long*)eiv)[threadIdx.x];
            unsigned bad = __ballot_sync(0xffffffffu, val < 0 || val >= NN);
            if (threadIdx.x == 0) {
                s_i32 = bad ? 1 : 0;
                if (blockIdx.x == GB) g_idx32 = s_i32;   // publish for later kernels
            }
        }
        __syncthreads();
        const int i32 = s_i32;
        const int gt = (blockIdx.x - GB) * 256 + threadIdx.x;
        const int T  = HB * 256;
        if (i32) {
            const int* ei32 = (const int*)eiv;
            for (int b = gt * 4; b < NE; b += T * 4) {
                int4 cc = __ldg((const int4*)(ei32 + NE + b));
                atomicAdd(&g_deg[cc.x], 1);
                atomicAdd(&g_deg[cc.y], 1);
                atomicAdd(&g_deg[cc.z], 1);
                atomicAdd(&g_deg[cc.w], 1);
            }
        } else {
            const long long* ei = (const long long*)eiv;
            for (int e = gt; e < NE; e += T) {
                int r = (int)ei[e];
                int c = (int)ei[NE + e];
                g_edges[e] = make_int2(r, c);
                atomicAdd(&g_deg[c], 1);
            }
        }
    }
}

// ---------------- scale: t4 *= dinv ; aggA = t4 (self-loop) ----------------
__global__ void __launch_bounds__(256) k_scale() {
    int v = blockIdx.x * blockDim.x + threadIdx.x;
    if (v >= NN) return;
    float d  = rsqrtf((float)(g_deg[v] + 1));
    float4 a = g_t4[v];
    float4 t = make_float4(a.x * d, a.y * d, a.z * d, a.w * d);
    g_t4[v]   = t;
    g_aggA[v] = t;
}

// ---------------- edge scatter: agg[row] += t4[col]  (2 edges/thread) ----------
template <int PHASE>   // 0: aggA, 1: aggB
__global__ void __launch_bounds__(256) k_scatter4(const int* __restrict__ ei32) {
    int base = (blockIdx.x * 256 + threadIdx.x) * 2;
    if (base >= NE) return;
    float4* agg = (PHASE == 0) ? g_aggA : g_aggB;
    int r0, c0, r1, c1;
    if (g_idx32) {
        int2 rr = __ldg((const int2*)(ei32 + base));
        int2 cc = __ldg((const int2*)(ei32 + NE + base));
        r0 = rr.x; r1 = rr.y; c0 = cc.x; c1 = cc.y;
    } else {
        int4 p = *(const int4*)(g_edges + base);
        r0 = p.x; c0 = p.y; r1 = p.z; c1 = p.w;
    }
    float4 v0 = __ldg(g_t4 + c0);
    float4 v1 = __ldg(g_t4 + c1);
    asm volatile("red.global.add.v4.f32 [%0], {%1,%2,%3,%4};"
                 :: "l"(agg + r0), "f"(v0.x), "f"(v0.y), "f"(v0.z), "f"(v0.w) : "memory");
    asm volatile("red.global.add.v4.f32 [%0], {%1,%2,%3,%4};"
                 :: "l"(agg + r1), "f"(v1.x), "f"(v1.y), "f"(v1.z), "f"(v1.w) : "memory");
}

__global__ void __launch_bounds__(256) k_scatter2(const int* __restrict__ ei32) {
    int base = (blockIdx.x * 256 + threadIdx.x) * 2;
    if (base >= NE) return;
    int r0, c0, r1, c1;
    if (g_idx32) {
        int2 rr = __ldg((const int2*)(ei32 + base));
        int2 cc = __ldg((const int2*)(ei32 + NE + base));
        r0 = rr.x; r1 = rr.y; c0 = cc.x; c1 = cc.y;
    } else {
        int4 p = *(const int4*)(g_edges + base);
        r0 = p.x; c0 = p.y; r1 = p.z; c1 = p.w;
    }
    float2 v0 = __ldg(g_t2 + c0);
    float2 v1 = __ldg(g_t2 + c1);
    asm volatile("red.global.add.v2.f32 [%0], {%1,%2};"
                 :: "l"(g_agg2 + r0), "f"(v0.x), "f"(v0.y) : "memory");
    asm volatile("red.global.add.v2.f32 [%0], {%1,%2};"
                 :: "l"(g_agg2 + r1), "f"(v1.x), "f"(v1.y) : "memory");
}

// ---------------- layer 2 transform ----------------
__global__ void __launch_bounds__(256) k_l2(const float* __restrict__ W2,
                                            const float* __restrict__ b1) {
    int v = blockIdx.x * blockDim.x + threadIdx.x;
    if (v >= NN) return;
    float d  = rsqrtf((float)(g_deg[v] + 1));
    float4 a = g_aggA[v];
    float h0 = tanhf(fmaf(a.x, d, __ldg(b1 + 0)));
    float h1 = tanhf(fmaf(a.y, d, __ldg(b1 + 1)));
    float h2 = tanhf(fmaf(a.z, d, __ldg(b1 + 2)));
    float h3 = tanhf(fmaf(a.w, d, __ldg(b1 + 3)));
    float t[4];
    #pragma unroll
    for (int j = 0; j < 4; j++)
        t[j] = (h0 * __ldg(W2 + j)     + h1 * __ldg(W2 + 4 + j)
              + h2 * __ldg(W2 + 8 + j) + h3 * __ldg(W2 + 12 + j)) * d;
    float4 tv = make_float4(t[0], t[1], t[2], t[3]);
    g_t4[v]   = tv;
    g_aggB[v] = tv;
}

// ---------------- layer 3 transform ----------------
__global__ void __launch_bounds__(256) k_l3(const float* __restrict__ W3,
                                            const float* __restrict__ b2) {
    int v = blockIdx.x * blockDim.x + threadIdx.x;
    if (v >= NN) return;
    float d  = rsqrtf((float)(g_deg[v] + 1));
    float4 a = g_aggB[v];
    float h0 = tanhf(fmaf(a.x, d, __ldg(b2 + 0)));
    float h1 = tanhf(fmaf(a.y, d, __ldg(b2 + 1)));
    float h2 = tanhf(fmaf(a.z, d, __ldg(b2 + 2)));
    float h3 = tanhf(fmaf(a.w, d, __ldg(b2 + 3)));
    float t0 = (h0 * __ldg(W3 + 0) + h1 * __ldg(W3 + 2)
              + h2 * __ldg(W3 + 4) + h3 * __ldg(W3 + 6)) * d;
    float t1 = (h0 * __ldg(W3 + 1) + h1 * __ldg(W3 + 3)
              + h2 * __ldg(W3 + 5) + h3 * __ldg(W3 + 7)) * d;
    float2 tv = make_float2(t0, t1);
    g_t2[v]   = tv;
    g_agg2[v] = tv;
}

// ---------------- epilogue ----------------
__global__ void __launch_bounds__(256) k_final(const float* __restrict__ b3,
                                               const float* __restrict__ Wc,
                                               const float* __restrict__ bc,
                                               float* __restrict__ out,
                                               int write_h) {
    int v = blockIdx.x * blockDim.x + threadIdx.x;
    if (v >= NN) return;
    float d  = rsqrtf((float)(g_deg[v] + 1));
    float2 a = g_agg2[v];
    float h0 = tanhf(fmaf(a.x, d, __ldg(b3 + 0)));
    float h1 = tanhf(fmaf(a.y, d, __ldg(b3 + 1)));
    float4 o;
    o.x = h0 * __ldg(Wc + 0) + h1 * __ldg(Wc + 4) + __ldg(bc + 0);
    o.y = h0 * __ldg(Wc + 1) + h1 * __ldg(Wc + 5) + __ldg(bc + 1);
    o.z = h0 * __ldg(Wc + 2) + h1 * __ldg(Wc + 6) + __ldg(bc + 2);
    o.w = h0 * __ldg(Wc + 3) + h1 * __ldg(Wc + 7) + __ldg(bc + 3);
    ((float4*)out)[v] = o;                                  // out [N,4]
    if (write_h)
        ((float2*)(out + 4 * NN))[v] = make_float2(h0, h1); // h [N,2]
}

// ---------------- host ----------------
extern "C" void kernel_launch(void* const* d_in, const int* in_sizes, int n_in,
                              void* d_out, int out_size) {
    const float* x  = (const float*)d_in[0];
    const void*  ei = d_in[1];
    const float* b1 = (const float*)d_in[3];
    const float* W1 = (const float*)d_in[2];
    const float* W2 = (const float*)d_in[4];
    const float* b2 = (const float*)d_in[5];
    const float* W3 = (const float*)d_in[6];
    const float* b3 = (const float*)d_in[7];
    const float* Wc = (const float*)d_in[8];
    const float* bc = (const float*)d_in[9];
    float* out = (float*)d_out;

    const int nbN  = (NN + 255) / 256;
    const int nbE2 = NE / (256 * 2);            // 2 edges/thread (exact: 6250)
    const int write_h = (out_size >= 6 * NN) ? 1 : 0;

    void* degp = nullptr;
    cudaGetSymbolAddress(&degp, g_deg);
    cudaMemsetAsync(degp, 0, NN * sizeof(int)); // deg counter; true degree = deg+1

    k_fused<<<GB + HB, 256>>>(ei, x, W1);       // GEMV || (detect + histogram)
    k_scale<<<nbN, 256>>>();

    k_scatter4<0><<<nbE2, 256>>>((const int*)ei);
    k_l2         <<<nbN, 256>>>(W2, b1);
    k_scatter4<1><<<nbE2, 256>>>((const int*)ei);
    k_l3         <<<nbN, 256>>>(W3, b2);
    k_scatter2   <<<nbE2, 256>>>((const int*)ei);
    k_final      <<<nbN, 256>>>(b3, Wc, bc, out, write_h);
}

// round 13
// speedup vs baseline: 1.3496x; 1.0275x over previous
#include <cuda_runtime.h>
#include <cuda_bf16.h>

#define NN 100000
#define NE 3200000

// Wait for the preceding (PDL-primary) kernel's memory to be visible.
#define GDC_WAIT() asm volatile("griddepcontrol.wait;" ::: "memory")

// ---------------- scratch (device globals: allocation-free) ----------------
__device__ int2   g_edges[NE];   // packed edges (int64 input path only)
__device__ int    g_deg[NN];     // zeroed by memsetAsync; true degree = g_deg+1
__device__ float4 g_t4[NN];      // scaled node features (gather source)
__device__ float4 g_aggA[NN];    // layer-1 accumulator
__device__ float4 g_aggB[NN];    // layer-2 accumulator
__device__ float2 g_t2[NN];      // layer-3 scaled features
__device__ float2 g_agg2[NN];    // layer-3 accumulator
__device__ int    g_idx32;       // 1 if edge_index is int32 (written by k_fused)

// ---------------- fused: GEMV (x@W1, unscaled) || degree histogram ----------------
#define GB 444
#define HB 444
__global__ void __launch_bounds__(256) k_fused(const void* __restrict__ eiv,
                                               const float* __restrict__ x,
                                               const float* __restrict__ W1) {
    if (blockIdx.x < GB) {
        __shared__ float sW[512];
        for (int i = threadIdx.x; i < 512; i += 256) sW[i] = W1[i];
        __syncthreads();
        const int lane = threadIdx.x & 31;
        const int warps = GB * 8;
        for (int v = (blockIdx.x * 256 + threadIdx.x) >> 5; v < NN; v += warps) {
            float4 xr = __ldg((const float4*)x + (size_t)v * 32 + lane);
            float xs[4] = {xr.x, xr.y, xr.z, xr.w};
            float acc[4] = {0.f, 0.f, 0.f, 0.f};
            #pragma unroll
            for (int i = 0; i < 4; i++) {
                int k = lane * 4 + i;
                #pragma unroll
                for (int j = 0; j < 4; j++) acc[j] += xs[i] * sW[k * 4 + j];
            }
            #pragma unroll
            for (int o = 16; o > 0; o >>= 1) {
                #pragma unroll
                for (int j = 0; j < 4; j++)
                    acc[j] += __shfl_xor_sync(0xffffffffu, acc[j], o);
            }
            if (lane == 0)
                g_t4[v] = make_float4(acc[0], acc[1], acc[2], acc[3]);  // unscaled
        }
    } else {
        __shared__ int s_i32;
        if (threadIdx.x < 32) {
            long long val = ((const long long*)eiv)[threadIdx.x];
            unsigned bad = __ballot_sync(0xffffffffu, val < 0 || val >= NN);
            if (threadIdx.x == 0) {
                s_i32 = bad ? 1 : 0;
                if (blockIdx.x == GB) g_idx32 = s_i32;   // publish for later kernels
            }
        }
        __syncthreads();
        const int i32 = s_i32;
        const int gt = (blockIdx.x - GB) * 256 + threadIdx.x;
        const int T  = HB * 256;
        if (i32) {
            const int* ei32 = (const int*)eiv;
            for (int b = gt * 4; b < NE; b += T * 4) {
                int4 cc = __ldg((const int4*)(ei32 + NE + b));
                atomicAdd(&g_deg[cc.x], 1);
                atomicAdd(&g_deg[cc.y], 1);
                atomicAdd(&g_deg[cc.z], 1);
                atomicAdd(&g_deg[cc.w], 1);
            }
        } else {
            const long long* ei = (const long long*)eiv;
            for (int e = gt; e < NE; e += T) {
                int r = (int)ei[e];
                int c = (int)ei[NE + e];
                g_edges[e] = make_int2(r, c);
                atomicAdd(&g_deg[c], 1);
            }
        }
    }
}

// ---------------- scale: t4 *= dinv ; aggA = t4 (self-loop) ----------------
__global__ void __launch_bounds__(256) k_scale() {
    int v = blockIdx.x * blockDim.x + threadIdx.x;
    GDC_WAIT();
    if (v >= NN) return;
    float d  = rsqrtf((float)(g_deg[v] + 1));
    float4 a = g_t4[v];
    float4 t = make_float4(a.x * d, a.y * d, a.z * d, a.w * d);
    g_t4[v]   = t;
    g_aggA[v] = t;
}

// ---------------- edge scatter: agg[row] += t4[col]  (2 edges/thread) ----------
template <int PHASE>   // 0: aggA, 1: aggB
__global__ void __launch_bounds__(256) k_scatter4(const int* __restrict__ ei32) {
    int base = (blockIdx.x * 256 + threadIdx.x) * 2;
    GDC_WAIT();
    if (base >= NE) return;
    float4* agg = (PHASE == 0) ? g_aggA : g_aggB;
    int r0, c0, r1, c1;
    if (g_idx32) {
        int2 rr = __ldg((const int2*)(ei32 + base));
        int2 cc = __ldg((const int2*)(ei32 + NE + base));
        r0 = rr.x; r1 = rr.y; c0 = cc.x; c1 = cc.y;
    } else {
        int4 p = *(const int4*)(g_edges + base);
        r0 = p.x; c0 = p.y; r1 = p.z; c1 = p.w;
    }
    float4 v0 = __ldg(g_t4 + c0);
    float4 v1 = __ldg(g_t4 + c1);
    asm volatile("red.global.add.v4.f32 [%0], {%1,%2,%3,%4};"
                 :: "l"(agg + r0), "f"(v0.x), "f"(v0.y), "f"(v0.z), "f"(v0.w) : "memory");
    asm volatile("red.global.add.v4.f32 [%0], {%1,%2,%3,%4};"
                 :: "l"(agg + r1), "f"(v1.x), "f"(v1.y), "f"(v1.z), "f"(v1.w) : "memory");
}

__global__ void __launch_bounds__(256) k_scatter2(const int* __restrict__ ei32) {
    int base = (blockIdx.x * 256 + threadIdx.x) * 2;
    GDC_WAIT();
    if (base >= NE) return;
    int r0, c0, r1, c1;
    if (g_idx32) {
        int2 rr = __ldg((const int2*)(ei32 + base));
        int2 cc = __ldg((const int2*)(ei32 + NE + base));
        r0 = rr.x; r1 = rr.y; c0 = cc.x; c1 = cc.y;
    } else {
        int4 p = *(const int4*)(g_edges + base);
        r0 = p.x; c0 = p.y; r1 = p.z; c1 = p.w;
    }
    float2 v0 = __ldg(g_t2 + c0);
    float2 v1 = __ldg(g_t2 + c1);
    asm volatile("red.global.add.v2.f32 [%0], {%1,%2};"
                 :: "l"(g_agg2 + r0), "f"(v0.x), "f"(v0.y) : "memory");
    asm volatile("red.global.add.v2.f32 [%0], {%1,%2};"
                 :: "l"(g_agg2 + r1), "f"(v1.x), "f"(v1.y) : "memory");
}

// ---------------- layer 2 transform ----------------
__global__ void __launch_bounds__(256) k_l2(const float* __restrict__ W2,
                                            const float* __restrict__ b1) {
    int v = blockIdx.x * blockDim.x + threadIdx.x;
    GDC_WAIT();
    if (v >= NN) return;
    float d  = rsqrtf((float)(g_deg[v] + 1));
    float4 a = g_aggA[v];
    float h0 = tanhf(fmaf(a.x, d, __ldg(b1 + 0)));
    float h1 = tanhf(fmaf(a.y, d, __ldg(b1 + 1)));
    float h2 = tanhf(fmaf(a.z, d, __ldg(b1 + 2)));
    float h3 = tanhf(fmaf(a.w, d, __ldg(b1 + 3)));
    float t[4];
    #pragma unroll
    for (int j = 0; j < 4; j++)
        t[j] = (h0 * __ldg(W2 + j)     + h1 * __ldg(W2 + 4 + j)
              + h2 * __ldg(W2 + 8 + j) + h3 * __ldg(W2 + 12 + j)) * d;
    float4 tv = make_float4(t[0], t[1], t[2], t[3]);
    g_t4[v]   = tv;
    g_aggB[v] = tv;
}

// ---------------- layer 3 transform ----------------
__global__ void __launch_bounds__(256) k_l3(const float* __restrict__ W3,
                                            const float* __restrict__ b2) {
    int v = blockIdx.x * blockDim.x + threadIdx.x;
    GDC_WAIT();
    if (v >= NN) return;
    float d  = rsqrtf((float)(g_deg[v] + 1));
    float4 a = g_aggB[v];
    float h0 = tanhf(fmaf(a.x, d, __ldg(b2 + 0)));
    float h1 = tanhf(fmaf(a.y, d, __ldg(b2 + 1)));
    float h2 = tanhf(fmaf(a.z, d, __ldg(b2 + 2)));
    float h3 = tanhf(fmaf(a.w, d, __ldg(b2 + 3)));
    float t0 = (h0 * __ldg(W3 + 0) + h1 * __ldg(W3 + 2)
              + h2 * __ldg(W3 + 4) + h3 * __ldg(W3 + 6)) * d;
    float t1 = (h0 * __ldg(W3 + 1) + h1 * __ldg(W3 + 3)
              + h2 * __ldg(W3 + 5) + h3 * __ldg(W3 + 7)) * d;
    float2 tv = make_float2(t0, t1);
    g_t2[v]   = tv;
    g_agg2[v] = tv;
}

// ---------------- epilogue ----------------
__global__ void __launch_bounds__(256) k_final(const float* __restrict__ b3,
                                               const float* __restrict__ Wc,
                                               const float* __restrict__ bc,
                                               float* __restrict__ out,
                                               int write_h) {
    int v = blockIdx.x * blockDim.x + threadIdx.x;
    GDC_WAIT();
    if (v >= NN) return;
    float d  = rsqrtf((float)(g_deg[v] + 1));
    float2 a = g_agg2[v];
    float h0 = tanhf(fmaf(a.x, d, __ldg(b3 + 0)));
    float h1 = tanhf(fmaf(a.y, d, __ldg(b3 + 1)));
    float4 o;
    o.x = h0 * __ldg(Wc + 0) + h1 * __ldg(Wc + 4) + __ldg(bc + 0);
    o.y = h0 * __ldg(Wc + 1) + h1 * __ldg(Wc + 5) + __ldg(bc + 1);
    o.z = h0 * __ldg(Wc + 2) + h1 * __ldg(Wc + 6) + __ldg(bc + 2);
    o.w = h0 * __ldg(Wc + 3) + h1 * __ldg(Wc + 7) + __ldg(bc + 3);
    ((float4*)out)[v] = o;                                  // out [N,4]
    if (write_h)
        ((float2*)(out + 4 * NN))[v] = make_float2(h0, h1); // h [N,2]
}

// ---------------- host ----------------
template <typename... Args>
static void launch_pdl(void (*kern)(Args...), int grid, int block, Args... args) {
    cudaLaunchConfig_t cfg = {};
    cfg.gridDim  = dim3(grid, 1, 1);
    cfg.blockDim = dim3(block, 1, 1);
    cudaLaunchAttribute attr[1];
    attr[0].id = cudaLaunchAttributeProgrammaticStreamSerialization;
    attr[0].val.programmaticStreamSerializationAllowed = 1;
    cfg.attrs = attr;
    cfg.numAttrs = 1;
    cudaLaunchKernelEx(&cfg, kern, args...);
}

extern "C" void kernel_launch(void* const* d_in, const int* in_sizes, int n_in,
                              void* d_out, int out_size) {
    const float* x  = (const float*)d_in[0];
    const void*  ei = d_in[1];
    const float* W1 = (const float*)d_in[2];
    const float* b1 = (const float*)d_in[3];
    const float* W2 = (const float*)d_in[4];
    const float* b2 = (const float*)d_in[5];
    const float* W3 = (const float*)d_in[6];
    const float* b3 = (const float*)d_in[7];
    const float* Wc = (const float*)d_in[8];
    const float* bc = (const float*)d_in[9];
    float* out = (float*)d_out;

    const int nbN  = (NN + 255) / 256;
    const int nbE2 = NE / (256 * 2);            // 2 edges/thread (exact: 6250)
    const int write_h = (out_size >= 6 * NN) ? 1 : 0;

    void* degp = nullptr;
    cudaGetSymbolAddress(&degp, g_deg);
    cudaMemsetAsync(degp, 0, NN * sizeof(int)); // deg counter; true degree = deg+1

    k_fused<<<GB + HB, 256>>>(ei, x, W1);       // GEMV || (detect + histogram)

    launch_pdl(k_scale, nbN, 256);
    launch_pdl(k_scatter4<0>, nbE2, 256, (const int*)ei);
    launch_pdl(k_l2, nbN, 256, W2, b1);
    launch_pdl(k_scatter4<1>, nbE2, 256, (const int*)ei);
    launch_pdl(k_l3, nbN, 256, W3, b2);
    launch_pdl(k_scatter2, nbE2, 256, (const int*)ei);
    launch_pdl(k_final, nbN, 256, b3, Wc, bc, out, write_h);
}